// round 1
// baseline (speedup 1.0000x reference)
#include <cuda_runtime.h>
#include <cstdint>
#include <math.h>

// Problem dims
static constexpr int BATCH = 2048;
static constexpr int SEQ   = 64;
static constexpr int DIN   = 512;
static constexpr int HID   = 1024;
static constexpr int N3    = 3 * HID;     // 3072 (f,g,h concatenated)
static constexpr int MT    = BATCH * SEQ; // 131072

// ---------------- device scratch (allocation-free rule: __device__ globals) ----
__device__ __align__(128) float g_Xr[(size_t)MT * DIN];   // tf32-rounded x      (268 MB)
__device__ __align__(128) float g_U [(size_t)MT * N3];    // x-part preacts      (1.61 GB)
__device__ __align__(128) float g_Wk[(size_t)N3 * DIN];   // W[:, :512]  rounded (6.3 MB)
__device__ __align__(128) float g_Wr[(size_t)N3 * HID];   // W[:, 512:]  rounded (12.6 MB)
__device__ __align__(128) float g_bias[N3];
__device__ __align__(128) float g_PRE[(size_t)BATCH * N3];
__device__ __align__(128) float g_Hbuf[2][(size_t)BATCH * HID];

// ---------------- helpers ------------------------------------------------------
__device__ __forceinline__ float tf32r(float v) {
    uint32_t o;
    asm("cvt.rna.tf32.f32 %0, %1;" : "=r"(o) : "f"(v));
    return __uint_as_float(o);
}

__device__ __forceinline__ void cpa16(void* sm, const void* gm) {
    uint32_t s = (uint32_t)__cvta_generic_to_shared(sm);
    asm volatile("cp.async.ca.shared.global [%0], [%1], 16;" :: "r"(s), "l"(gm));
}
__device__ __forceinline__ void cp_commit() { asm volatile("cp.async.commit_group;"); }
template<int N> __device__ __forceinline__ void cp_wait() {
    asm volatile("cp.async.wait_group %0;" :: "n"(N));
}

__device__ __forceinline__ void mma8(float* c, const float* a, float b0, float b1) {
    asm volatile(
        "mma.sync.aligned.m16n8k8.row.col.f32.tf32.tf32.f32 "
        "{%0,%1,%2,%3},{%4,%5,%6,%7},{%8,%9},{%0,%1,%2,%3};"
        : "+f"(c[0]), "+f"(c[1]), "+f"(c[2]), "+f"(c[3])
        : "r"(__float_as_uint(a[0])), "r"(__float_as_uint(a[1])),
          "r"(__float_as_uint(a[2])), "r"(__float_as_uint(a[3])),
          "r"(__float_as_uint(b0)),  "r"(__float_as_uint(b1)));
}

// ---------------- weight repack + rounding ------------------------------------
__global__ void repack_k(const float* __restrict__ Wf, const float* __restrict__ bf,
                         const float* __restrict__ Wg, const float* __restrict__ bg,
                         const float* __restrict__ Wh, const float* __restrict__ bh,
                         float* __restrict__ wk, float* __restrict__ wr,
                         float* __restrict__ bias) {
    int idx = blockIdx.x * blockDim.x + threadIdx.x;
    const int TOT = N3 * (DIN + HID);
    if (idx < TOT) {
        int n = idx / (DIN + HID);
        int k = idx - n * (DIN + HID);
        int sel = n >> 10, row = n & (HID - 1);
        const float* W = (sel == 0) ? Wf : (sel == 1) ? Wg : Wh;
        float v = tf32r(W[(size_t)row * (DIN + HID) + k]);
        if (k < DIN) wk[(size_t)n * DIN + k] = v;
        else         wr[(size_t)n * HID + (k - DIN)] = v;
    } else if (idx < TOT + N3) {
        int n = idx - TOT;
        int sel = n >> 10, row = n & (HID - 1);
        bias[n] = ((sel == 0) ? bf : (sel == 1) ? bg : bh)[row];
    }
}

__global__ void roundx_k(const float4* __restrict__ x, float4* __restrict__ xr, int n4) {
    int i = blockIdx.x * blockDim.x + threadIdx.x;
    if (i < n4) {
        float4 v = x[i];
        v.x = tf32r(v.x); v.y = tf32r(v.y); v.z = tf32r(v.z); v.w = tf32r(v.w);
        xr[i] = v;
    }
}

// ---------------- tf32 warp-MMA GEMM: C[M,N] = A[M,K] @ Bw[N,K]^T (+addend,+bias)
// BM=BN=128, BK=16, 256 threads (8 warps, 4x2), warp tile 32x64.
__global__ __launch_bounds__(256, 1) void gemm_tf32(
    const float* __restrict__ A, const float* __restrict__ Bw, float* __restrict__ C,
    const float* __restrict__ addend, int addStride,
    const float* __restrict__ bias, int M, int N, int K) {
    __shared__ float As[2][128][20];
    __shared__ float Bs[2][128][20];
    const int tid = threadIdx.x, lane = tid & 31, warp = tid >> 5;
    const int wm = warp >> 1, wn = warp & 1;
    const int bm = blockIdx.y, bn = blockIdx.x;
    const float* Ag = A  + (size_t)bm * 128 * K;
    const float* Bg = Bw + (size_t)bn * 128 * K;
    const int rr = tid >> 2, cc = (tid & 3) * 4;

    float acc[2][8][4];
#pragma unroll
    for (int i = 0; i < 2; i++)
#pragma unroll
        for (int j = 0; j < 8; j++)
#pragma unroll
            for (int k = 0; k < 4; k++) acc[i][j][k] = 0.f;

    auto load = [&](int s, int kt) {
        int k0 = kt * 16;
#pragma unroll
        for (int i = 0; i < 2; i++) {
            int r = i * 64 + rr;
            cpa16(&As[s][r][cc], Ag + (size_t)r * K + k0 + cc);
            cpa16(&Bs[s][r][cc], Bg + (size_t)r * K + k0 + cc);
        }
    };

    const int KT = K >> 4;
    load(0, 0); cp_commit();
    for (int kt = 0; kt < KT; ++kt) {
        if (kt + 1 < KT) { load((kt + 1) & 1, kt + 1); cp_commit(); cp_wait<1>(); }
        else             { cp_wait<0>(); }
        __syncthreads();
        int s = kt & 1;
#pragma unroll
        for (int kk = 0; kk < 16; kk += 8) {
            float a[2][4];
#pragma unroll
            for (int mt = 0; mt < 2; mt++) {
                int r = wm * 32 + mt * 16 + (lane >> 2);
                int c = kk + (lane & 3);
                a[mt][0] = As[s][r][c];     a[mt][1] = As[s][r + 8][c];
                a[mt][2] = As[s][r][c + 4]; a[mt][3] = As[s][r + 8][c + 4];
            }
#pragma unroll
            for (int nt = 0; nt < 8; nt++) {
                int n = wn * 64 + nt * 8 + (lane >> 2);
                float b0 = Bs[s][n][kk + (lane & 3)];
                float b1 = Bs[s][n][kk + 4 + (lane & 3)];
                mma8(acc[0][nt], a[0], b0, b1);
                mma8(acc[1][nt], a[1], b0, b1);
            }
        }
        __syncthreads();
    }

    // epilogue
#pragma unroll
    for (int mt = 0; mt < 2; mt++) {
#pragma unroll
        for (int nt = 0; nt < 8; nt++) {
            int r0 = bm * 128 + wm * 32 + mt * 16 + (lane >> 2);
            int c0 = bn * 128 + wn * 64 + nt * 8 + (lane & 3) * 2;
#pragma unroll
            for (int i = 0; i < 2; i++) {
                int rg = r0 + i * 8;
#pragma unroll
                for (int j = 0; j < 2; j++) {
                    int cg = c0 + j;
                    float v = acc[mt][nt][i * 2 + j];
                    if (addend) v += addend[(size_t)rg * addStride + cg];
                    if (bias)   v += bias[cg];
                    C[(size_t)rg * N + cg] = v;
                }
            }
        }
    }
}

// ---------------- gated combine: h = sig(-f)*g + (1-sig(-f))*hh ----------------
__global__ void combine_k(const float* __restrict__ pre, int stride,
                          float* __restrict__ hout) {
    int idx = blockIdx.x * blockDim.x + threadIdx.x;
    if (idx >= BATCH * HID) return;
    int b = idx >> 10, j = idx & (HID - 1);
    const float* row = pre + (size_t)b * stride;
    float f  = row[j];
    float g  = row[HID + j];
    float hh = row[2 * HID + j];
    float gate = 1.f / (1.f + expf(f));     // sigmoid(-f)
    float hn = hh + gate * (g - hh);
    hout[idx] = tf32r(hn);                  // pre-round for next step's tf32 MMA
}

// ---------------- final FC: out[B,2] = h @ Wfc^T + bfc -------------------------
__global__ void final_k(const float* __restrict__ h, const float* __restrict__ Wfc,
                        const float* __restrict__ bfc, float* __restrict__ out) {
    int b = blockIdx.x;
    float s0 = 0.f, s1 = 0.f;
    for (int j = threadIdx.x; j < HID; j += blockDim.x) {
        float hv = h[(size_t)b * HID + j];
        s0 += hv * Wfc[j];
        s1 += hv * Wfc[HID + j];
    }
#pragma unroll
    for (int o = 16; o > 0; o >>= 1) {
        s0 += __shfl_down_sync(0xFFFFFFFFu, s0, o);
        s1 += __shfl_down_sync(0xFFFFFFFFu, s1, o);
    }
    __shared__ float sm[2][8];
    int warp = threadIdx.x >> 5, lane = threadIdx.x & 31;
    if (lane == 0) { sm[0][warp] = s0; sm[1][warp] = s1; }
    __syncthreads();
    if (threadIdx.x == 0) {
        float t0 = 0.f, t1 = 0.f;
        int nw = blockDim.x >> 5;
        for (int w = 0; w < nw; w++) { t0 += sm[0][w]; t1 += sm[1][w]; }
        out[b * 2 + 0] = t0 + bfc[0];
        out[b * 2 + 1] = t1 + bfc[1];
    }
}

// ---------------- launch --------------------------------------------------------
extern "C" void kernel_launch(void* const* d_in, const int* in_sizes, int n_in,
                              void* d_out, int out_size) {
    const float* x   = (const float*)d_in[0];
    const float* Wf  = (const float*)d_in[1];
    const float* bf  = (const float*)d_in[2];
    const float* Wg  = (const float*)d_in[3];
    const float* bg  = (const float*)d_in[4];
    const float* Wh  = (const float*)d_in[5];
    const float* bh  = (const float*)d_in[6];
    const float* Wfc = (const float*)d_in[7];
    const float* bfc = (const float*)d_in[8];

    float *pXr, *pU, *pWk, *pWr, *pBias, *pPRE, *pH;
    cudaGetSymbolAddress((void**)&pXr,  g_Xr);
    cudaGetSymbolAddress((void**)&pU,   g_U);
    cudaGetSymbolAddress((void**)&pWk,  g_Wk);
    cudaGetSymbolAddress((void**)&pWr,  g_Wr);
    cudaGetSymbolAddress((void**)&pBias,g_bias);
    cudaGetSymbolAddress((void**)&pPRE, g_PRE);
    cudaGetSymbolAddress((void**)&pH,   g_Hbuf);
    float* pH0 = pH;
    float* pH1 = pH + (size_t)BATCH * HID;

    // 1) repack + round weights; round x
    {
        int tot = N3 * (DIN + HID) + N3;
        repack_k<<<(tot + 255) / 256, 256>>>(Wf, bf, Wg, bg, Wh, bh, pWk, pWr, pBias);
        int n4 = MT * DIN / 4;
        roundx_k<<<(n4 + 255) / 256, 256>>>((const float4*)x, (float4*)pXr, n4);
    }

    // 2) parallel x-part: U[b*T+t, :] = x_t @ Wk^T + bias
    gemm_tf32<<<dim3(N3 / 128, MT / 128), 256>>>(
        pXr, pWk, pU, nullptr, 0, pBias, MT, N3, DIN);

    // 3) step 0: h0 = 0 so PRE = U[t=0] directly
    combine_k<<<(BATCH * HID) / 256, 256>>>(pU, SEQ * N3, pH0);

    // 4) recurrence
    for (int t = 1; t < SEQ; t++) {
        float* hprev = ((t - 1) & 1) ? pH1 : pH0;
        float* hnext = (t & 1) ? pH1 : pH0;
        gemm_tf32<<<dim3(N3 / 128, BATCH / 128), 256>>>(
            hprev, pWr, pPRE, pU + (size_t)t * N3, SEQ * N3, nullptr,
            BATCH, N3, HID);
        combine_k<<<(BATCH * HID) / 256, 256>>>(pPRE, N3, hnext);
    }

    // 5) final FC (fp32 exact)
    final_k<<<BATCH, 256>>>(pH1, Wfc, bfc, (float*)d_out);
}

// round 3
// speedup vs baseline: 1.2153x; 1.2153x over previous
#include <cuda_runtime.h>
#include <cstdint>
#include <math.h>

// ---------------- problem dims -------------------------------------------------
static constexpr int BATCH = 2048;
static constexpr int SEQ   = 64;
static constexpr int DIN   = 512;
static constexpr int HID   = 1024;
static constexpr int N3    = 3 * HID;      // 3072
static constexpr int MT    = BATCH * SEQ;  // 131072

// ---------------- GEMM tile config ---------------------------------------------
static constexpr int BM = 128;
static constexpr int BN = 192;             // 64 f | 64 g | 64 h
static constexpr int BK = 32;              // 128 B per row per stage
static constexpr int THREADS = 512;        // 16 warps: 4 (m) x 4 (n)
static constexpr int A_BYTES = BM * BK * 4;        // 16 KB
static constexpr int B_BYTES = BN * BK * 4;        // 24 KB
static constexpr int STAGE_BYTES = A_BYTES + B_BYTES;  // 40 KB
static constexpr int STAGES = 3;
static constexpr int SMEM_TOTAL = STAGES * STAGE_BYTES;   // 120 KB (combine reuses it)
static constexpr int CSTRIDE = 200;        // combine-buffer row stride (floats)

// ---------------- device scratch ------------------------------------------------
__device__ __align__(128) float g_Xr[(size_t)MT * DIN];
__device__ __align__(128) float g_U [(size_t)MT * N3];
__device__ __align__(128) float g_Wk[(size_t)N3 * DIN];
__device__ __align__(128) float g_Wr[(size_t)N3 * HID];
__device__ __align__(128) float g_bias[N3];
__device__ __align__(128) float g_H[2][(size_t)BATCH * HID];

// ---------------- helpers --------------------------------------------------------
__device__ __forceinline__ uint32_t smem_u32(const void* p) {
    uint32_t a;
    asm("{ .reg .u64 t; cvta.to.shared.u64 t, %1; cvt.u32.u64 %0, t; }" : "=r"(a) : "l"(p));
    return a;
}
__device__ __forceinline__ float tf32r(float v) {
    uint32_t o;
    asm("cvt.rna.tf32.f32 %0, %1;" : "=r"(o) : "f"(v));
    return __uint_as_float(o);
}
__device__ __forceinline__ void cpa16(uint32_t s, const void* g) {
    asm volatile("cp.async.cg.shared.global [%0], [%1], 16;" :: "r"(s), "l"(g));
}
__device__ __forceinline__ void cp_commit() { asm volatile("cp.async.commit_group;"); }
template<int N> __device__ __forceinline__ void cp_wait() {
    asm volatile("cp.async.wait_group %0;" :: "n"(N));
}
__device__ __forceinline__ float4 lds128(uint32_t a) {
    float4 v;
    asm volatile("ld.shared.v4.f32 {%0,%1,%2,%3}, [%4];"
                 : "=f"(v.x), "=f"(v.y), "=f"(v.z), "=f"(v.w) : "r"(a));
    return v;
}
__device__ __forceinline__ void sts64(uint32_t a, float x, float y) {
    asm volatile("st.shared.v2.f32 [%0], {%1,%2};" :: "r"(a), "f"(x), "f"(y));
}
__device__ __forceinline__ void mma8(float* c, const float* a, float b0, float b1) {
    asm volatile(
        "mma.sync.aligned.m16n8k8.row.col.f32.tf32.tf32.f32 "
        "{%0,%1,%2,%3},{%4,%5,%6,%7},{%8,%9},{%0,%1,%2,%3};"
        : "+f"(c[0]), "+f"(c[1]), "+f"(c[2]), "+f"(c[3])
        : "r"(__float_as_uint(a[0])), "r"(__float_as_uint(a[1])),
          "r"(__float_as_uint(a[2])), "r"(__float_as_uint(a[3])),
          "r"(__float_as_uint(b0)),  "r"(__float_as_uint(b1)));
}

// ---------------- weight repack (columns grouped 64f|64g|64h per 192) ----------
__global__ void repack_k(const float* __restrict__ Wf, const float* __restrict__ bf,
                         const float* __restrict__ Wg, const float* __restrict__ bg,
                         const float* __restrict__ Wh, const float* __restrict__ bh,
                         float* __restrict__ wk, float* __restrict__ wr,
                         float* __restrict__ bias) {
    int idx = blockIdx.x * blockDim.x + threadIdx.x;
    const int CIN = DIN + HID;
    const int TOT = N3 * CIN;
    if (idx < TOT) {
        int n = idx / CIN;
        int k = idx - n * CIN;
        int gi = n / 192, rem = n % 192, p = rem >> 6, jj = rem & 63;
        int j = gi * 64 + jj;
        const float* W = (p == 0) ? Wf : (p == 1) ? Wg : Wh;
        float v = tf32r(W[(size_t)j * CIN + k]);
        if (k < DIN) wk[(size_t)n * DIN + k] = v;
        else         wr[(size_t)n * HID + (k - DIN)] = v;
    } else if (idx < TOT + N3) {
        int n = idx - TOT;
        int gi = n / 192, rem = n % 192, p = rem >> 6, jj = rem & 63;
        int j = gi * 64 + jj;
        bias[n] = ((p == 0) ? bf : (p == 1) ? bg : bh)[j];
    }
}

__global__ void roundx_k(const float4* __restrict__ x, float4* __restrict__ xr, int n4) {
    int i = blockIdx.x * blockDim.x + threadIdx.x;
    if (i < n4) {
        float4 v = x[i];
        v.x = tf32r(v.x); v.y = tf32r(v.y); v.z = tf32r(v.z); v.w = tf32r(v.w);
        xr[i] = v;
    }
}

// ---------------- tf32 warp-MMA GEMM: C[M,3072] = A[M,K] @ Bw[3072,K]^T ----------
// K-slot remap: mma step j, slot s  <->  physical k = 4*s + j (A and B agree).
// Each thread's fragments for all 4 steps = two contiguous float4 per row.
// SMEM: [row][32 floats], 16B chunk c stored at c ^ ((row&1)<<2)  (conflict-free).
// MODE 0: write acc + bias (full 128x192 tile) to out.
// MODE 1: stage acc tile to smem, gate-combine with U addend, write h (128x64).
template<int K, int MODE>
__global__ __launch_bounds__(THREADS, 1)
void lnn_gemm(const float* __restrict__ A, const float* __restrict__ Bw,
              float* __restrict__ out, const float* __restrict__ add,
              int addStride, const float* __restrict__ bias) {
    extern __shared__ __align__(1024) char smem[];
    const uint32_t sb = smem_u32(smem);
    const int tid = threadIdx.x, lane = tid & 31, wid = tid >> 5;
    const int wm = wid >> 2, wn = wid & 3;
    const int bn = blockIdx.x, bm = blockIdx.y;
    const int c = lane & 3, rq = lane >> 2;

    const char* Ag = (const char*)(A  + (size_t)bm * BM * K);
    const char* Bg = (const char*)(Bw + (size_t)bn * BN * K);

    auto load_stage = [&](int s, int kt) {
        uint32_t base = sb + s * STAGE_BYTES;
#pragma unroll
        for (int i = 0; i < 5; i++) {
            int q = tid + i * THREADS;          // 2560 chunks of 16B
            int row = q >> 3, ch = q & 7;
            if (row < BM) {
                int phys = ch ^ ((row & 1) << 2);
                cpa16(base + row * 128 + phys * 16,
                      Ag + (size_t)row * (K * 4) + (size_t)kt * 128 + ch * 16);
            } else {
                int r = row - BM;
                int phys = ch ^ ((r & 1) << 2);
                cpa16(base + A_BYTES + r * 128 + phys * 16,
                      Bg + (size_t)r * (K * 4) + (size_t)kt * 128 + ch * 16);
            }
        }
    };

    float acc[2][6][4];
#pragma unroll
    for (int a = 0; a < 2; a++)
#pragma unroll
        for (int b = 0; b < 6; b++)
#pragma unroll
            for (int d = 0; d < 4; d++) acc[a][b][d] = 0.f;

    const int KT = K / BK;
    load_stage(0, 0); cp_commit();
    load_stage(1, 1); cp_commit();

    for (int kt = 0; kt < KT; ++kt) {
        cp_wait<1>();
        __syncthreads();          // stage kt ready; all warps done with stage kt-1
        if (kt + 2 < KT) load_stage((kt + 2) % STAGES, kt + 2);
        cp_commit();

        uint32_t ab = sb + (kt % STAGES) * STAGE_BYTES;
        uint32_t bb = ab + A_BYTES;

        // A fragments: [mt][half] float4, rows rl / rl+8 (same swizzle parity)
        float4 aL[2][2], aH[2][2];
#pragma unroll
        for (int mt = 0; mt < 2; mt++) {
            int rl = wm * 32 + mt * 16 + rq, rh = rl + 8;
            int m0 = (rl & 1) << 2;
#pragma unroll
            for (int h = 0; h < 2; h++) {
                int ch = (c + h * 4) ^ m0;
                aL[mt][h] = lds128(ab + rl * 128 + ch * 16);
                aH[mt][h] = lds128(ab + rh * 128 + ch * 16);
            }
        }
#pragma unroll
        for (int nt = 0; nt < 6; nt++) {
            int n = wn * 48 + nt * 8 + rq;
            int ms = (n & 1) << 2;
            float4 bLv = lds128(bb + n * 128 + ((c ^ ms)) * 16);
            float4 bHv = lds128(bb + n * 128 + (((c + 4) ^ ms)) * 16);
            const float* bl = &bLv.x;
            const float* bh = &bHv.x;
#pragma unroll
            for (int j = 0; j < 4; j++) {
                float a0[4] = { ((const float*)&aL[0][0])[j], ((const float*)&aH[0][0])[j],
                                ((const float*)&aL[0][1])[j], ((const float*)&aH[0][1])[j] };
                mma8(acc[0][nt], a0, bl[j], bh[j]);
                float a1[4] = { ((const float*)&aL[1][0])[j], ((const float*)&aH[1][0])[j],
                                ((const float*)&aL[1][1])[j], ((const float*)&aH[1][1])[j] };
                mma8(acc[1][nt], a1, bl[j], bh[j]);
            }
        }
    }
    cp_wait<0>();

    if (MODE == 0) {
#pragma unroll
        for (int mt = 0; mt < 2; mt++) {
#pragma unroll
            for (int nt = 0; nt < 6; nt++) {
                int rl = bm * BM + wm * 32 + mt * 16 + rq, rh = rl + 8;
                int cl = bn * BN + wn * 48 + nt * 8 + c * 2;
                float b0 = bias[cl], b1 = bias[cl + 1];
                float2 v0 = make_float2(acc[mt][nt][0] + b0, acc[mt][nt][1] + b1);
                float2 v1 = make_float2(acc[mt][nt][2] + b0, acc[mt][nt][3] + b1);
                *(float2*)(out + (size_t)rl * N3 + cl) = v0;
                *(float2*)(out + (size_t)rh * N3 + cl) = v1;
            }
        }
    } else {
        __syncthreads();          // all compute done; safe to reuse stage smem
#pragma unroll
        for (int mt = 0; mt < 2; mt++) {
#pragma unroll
            for (int nt = 0; nt < 6; nt++) {
                int rl = wm * 32 + mt * 16 + rq, rh = rl + 8;
                int cl = wn * 48 + nt * 8 + c * 2;
                sts64(sb + (uint32_t)(rl * CSTRIDE + cl) * 4, acc[mt][nt][0], acc[mt][nt][1]);
                sts64(sb + (uint32_t)(rh * CSTRIDE + cl) * 4, acc[mt][nt][2], acc[mt][nt][3]);
            }
        }
        __syncthreads();
        int row0 = tid >> 4, grp = tid & 15;
#pragma unroll
        for (int rep = 0; rep < 4; rep++) {
            int r = row0 + rep * 32;
            float4 fv = lds128(sb + (uint32_t)(r * CSTRIDE + grp * 4) * 4);
            float4 gv = lds128(sb + (uint32_t)(r * CSTRIDE + 64 + grp * 4) * 4);
            float4 hv = lds128(sb + (uint32_t)(r * CSTRIDE + 128 + grp * 4) * 4);
            int gm = bm * BM + r;
            const float* ur = add + (size_t)gm * addStride + bn * BN;
            float4 uf = *(const float4*)(ur + grp * 4);
            float4 ug = *(const float4*)(ur + 64 + grp * 4);
            float4 uh = *(const float4*)(ur + 128 + grp * 4);
            float4 o;
            {
                float f = fv.x + uf.x, g = gv.x + ug.x, h = hv.x + uh.x;
                float gate = 1.f / (1.f + expf(f));
                o.x = tf32r(h + gate * (g - h));
            }
            {
                float f = fv.y + uf.y, g = gv.y + ug.y, h = hv.y + uh.y;
                float gate = 1.f / (1.f + expf(f));
                o.y = tf32r(h + gate * (g - h));
            }
            {
                float f = fv.z + uf.z, g = gv.z + ug.z, h = hv.z + uh.z;
                float gate = 1.f / (1.f + expf(f));
                o.z = tf32r(h + gate * (g - h));
            }
            {
                float f = fv.w + uf.w, g = gv.w + ug.w, h = hv.w + uh.w;
                float gate = 1.f / (1.f + expf(f));
                o.w = tf32r(h + gate * (g - h));
            }
            *(float4*)(out + (size_t)gm * HID + bn * 64 + grp * 4) = o;
        }
    }
}

// ---------------- step 0 combine (h0 = 0): pre = U[t=0] -------------------------
__global__ void combine0_k(const float* __restrict__ U, float* __restrict__ hout) {
    int idx = blockIdx.x * blockDim.x + threadIdx.x;
    if (idx >= BATCH * HID) return;
    int b = idx >> 10, j = idx & (HID - 1);
    int gi = j >> 6, jj = j & 63;
    const float* r = U + (size_t)b * SEQ * N3 + gi * 192;
    float f = r[jj], g = r[64 + jj], hh = r[128 + jj];
    float gate = 1.f / (1.f + expf(f));
    hout[idx] = tf32r(hh + gate * (g - hh));
}

// ---------------- final FC ------------------------------------------------------
__global__ void final_k(const float* __restrict__ h, const float* __restrict__ Wfc,
                        const float* __restrict__ bfc, float* __restrict__ out) {
    int b = blockIdx.x;
    float s0 = 0.f, s1 = 0.f;
    for (int j = threadIdx.x; j < HID; j += blockDim.x) {
        float hv = h[(size_t)b * HID + j];
        s0 += hv * Wfc[j];
        s1 += hv * Wfc[HID + j];
    }
#pragma unroll
    for (int o = 16; o > 0; o >>= 1) {
        s0 += __shfl_down_sync(0xFFFFFFFFu, s0, o);
        s1 += __shfl_down_sync(0xFFFFFFFFu, s1, o);
    }
    __shared__ float sm[2][8];
    int warp = threadIdx.x >> 5, lane = threadIdx.x & 31;
    if (lane == 0) { sm[0][warp] = s0; sm[1][warp] = s1; }
    __syncthreads();
    if (threadIdx.x == 0) {
        float t0 = 0.f, t1 = 0.f;
        int nw = blockDim.x >> 5;
        for (int w = 0; w < nw; w++) { t0 += sm[0][w]; t1 += sm[1][w]; }
        out[b * 2 + 0] = t0 + bfc[0];
        out[b * 2 + 1] = t1 + bfc[1];
    }
}

// ---------------- launch ---------------------------------------------------------
extern "C" void kernel_launch(void* const* d_in, const int* in_sizes, int n_in,
                              void* d_out, int out_size) {
    const float* x   = (const float*)d_in[0];
    const float* Wf  = (const float*)d_in[1];
    const float* bf  = (const float*)d_in[2];
    const float* Wg  = (const float*)d_in[3];
    const float* bg  = (const float*)d_in[4];
    const float* Wh  = (const float*)d_in[5];
    const float* bh  = (const float*)d_in[6];
    const float* Wfc = (const float*)d_in[7];
    const float* bfc = (const float*)d_in[8];

    float *pXr, *pU, *pWk, *pWr, *pBias, *pH;
    cudaGetSymbolAddress((void**)&pXr,  g_Xr);
    cudaGetSymbolAddress((void**)&pU,   g_U);
    cudaGetSymbolAddress((void**)&pWk,  g_Wk);
    cudaGetSymbolAddress((void**)&pWr,  g_Wr);
    cudaGetSymbolAddress((void**)&pBias,g_bias);
    cudaGetSymbolAddress((void**)&pH,   g_H);
    float* pH0 = pH;
    float* pH1 = pH + (size_t)BATCH * HID;

    cudaFuncSetAttribute(lnn_gemm<DIN, 0>, cudaFuncAttributeMaxDynamicSharedMemorySize, SMEM_TOTAL);
    cudaFuncSetAttribute(lnn_gemm<HID, 1>, cudaFuncAttributeMaxDynamicSharedMemorySize, SMEM_TOTAL);

    // 1) repack + round weights; round x
    {
        int tot = N3 * (DIN + HID) + N3;
        repack_k<<<(tot + 255) / 256, 256>>>(Wf, bf, Wg, bg, Wh, bh, pWk, pWr, pBias);
        int n4 = MT * DIN / 4;
        roundx_k<<<(n4 + 255) / 256, 256>>>((const float4*)x, (float4*)pXr, n4);
    }

    // 2) parallel x-part preacts: U = Xr @ Wk^T + bias
    lnn_gemm<DIN, 0><<<dim3(N3 / BN, MT / BM), THREADS, SMEM_TOTAL>>>(
        pXr, pWk, pU, nullptr, 0, pBias);

    // 3) t=0 (h0 = 0)
    combine0_k<<<(BATCH * HID) / 256, 256>>>(pU, pH0);

    // 4) recurrence with fused gate epilogue
    for (int t = 1; t < SEQ; t++) {
        float* hprev = ((t - 1) & 1) ? pH1 : pH0;
        float* hnext = (t & 1) ? pH1 : pH0;
        lnn_gemm<HID, 1><<<dim3(N3 / BN, BATCH / BM), THREADS, SMEM_TOTAL>>>(
            hprev, pWr, hnext, pU + (size_t)t * N3, SEQ * N3, nullptr);
    }

    // 5) final FC (fp32 exact)
    final_k<<<BATCH, 256>>>(pH1, Wfc, bfc, (float*)d_out);
}

// round 5
// speedup vs baseline: 2.9233x; 2.4055x over previous
#include <cuda_runtime.h>
#include <cuda_fp16.h>
#include <cstdint>
#include <math.h>

// ---------------- problem dims -------------------------------------------------
static constexpr int BATCH = 2048;
static constexpr int SEQ   = 64;
static constexpr int DIN   = 512;
static constexpr int HID   = 1024;
static constexpr int N3    = 3 * HID;      // 3072
static constexpr int MT    = BATCH * SEQ;  // 131072

// ---------------- GEMM tile config ---------------------------------------------
static constexpr int BM = 128;
static constexpr int BN = 384;             // 2 groups of (32f|32g|32h)x2 warp-halves
static constexpr int BK = 32;              // 32 halves = 64 B per row per stage
static constexpr int THREADS = 512;        // 16 warps: 4 (m) x 4 (n); warp tile 32x96
static constexpr int STAGES = 3;
static constexpr int A_BYTES = BM * BK * 2;            // 8 KB
static constexpr int B_BYTES = BN * BK * 2;            // 24 KB
static constexpr int STAGE_BYTES = A_BYTES + B_BYTES;  // 32 KB
static constexpr int SMEM_TOTAL = STAGES * STAGE_BYTES; // 96 KB

// ---------------- device scratch -------------------------------------------------
__device__ __align__(128) __half g_Xh[(size_t)MT * DIN];
__device__ __align__(128) __half g_U [(size_t)MT * N3];
__device__ __align__(128) __half g_Wk[(size_t)N3 * DIN];
__device__ __align__(128) __half g_Wr[(size_t)N3 * HID];
__device__ __align__(128) float  g_bias[N3];
__device__ __align__(128) __half g_H[2][(size_t)BATCH * HID];

// ---------------- helpers ---------------------------------------------------------
__device__ __forceinline__ uint32_t smem_u32(const void* p) {
    uint32_t a;
    asm("{ .reg .u64 t; cvta.to.shared.u64 t, %1; cvt.u32.u64 %0, t; }" : "=r"(a) : "l"(p));
    return a;
}
__device__ __forceinline__ void cpa16(uint32_t s, const void* g) {
    asm volatile("cp.async.cg.shared.global [%0], [%1], 16;" :: "r"(s), "l"(g));
}
__device__ __forceinline__ void cp_commit() { asm volatile("cp.async.commit_group;"); }
template<int N> __device__ __forceinline__ void cp_wait() {
    asm volatile("cp.async.wait_group %0;" :: "n"(N));
}
__device__ __forceinline__ void ldm4(uint32_t* r, uint32_t a) {
    asm volatile("ldmatrix.sync.aligned.m8n8.x4.shared.b16 {%0,%1,%2,%3}, [%4];"
                 : "=r"(r[0]), "=r"(r[1]), "=r"(r[2]), "=r"(r[3]) : "r"(a));
}
__device__ __forceinline__ void mma16(float* c, const uint32_t* a, uint32_t b0, uint32_t b1) {
    asm volatile(
        "mma.sync.aligned.m16n8k16.row.col.f32.f16.f16.f32 "
        "{%0,%1,%2,%3},{%4,%5,%6,%7},{%8,%9},{%0,%1,%2,%3};"
        : "+f"(c[0]), "+f"(c[1]), "+f"(c[2]), "+f"(c[3])
        : "r"(a[0]), "r"(a[1]), "r"(a[2]), "r"(a[3]), "r"(b0), "r"(b1));
}

// ---------------- weight repack --------------------------------------------------
// Repacked row n -> original column j of part (f/g/h):
//   gi = n/192, rem = n%192, wh = rem/96, part = (rem%96)/32, c = rem%32
//   j = gi*64 + wh*32 + c
__global__ void repack_k(const float* __restrict__ Wf, const float* __restrict__ bf,
                         const float* __restrict__ Wg, const float* __restrict__ bg,
                         const float* __restrict__ Wh, const float* __restrict__ bh,
                         __half* __restrict__ wk, __half* __restrict__ wr,
                         float* __restrict__ bias) {
    int idx = blockIdx.x * blockDim.x + threadIdx.x;
    const int CIN = DIN + HID;
    const int TOT = N3 * CIN;
    if (idx < TOT) {
        int n = idx / CIN;
        int k = idx - n * CIN;
        int gi = n / 192, rem = n % 192;
        int wh = rem / 96, rem2 = rem % 96, part = rem2 >> 5, c = rem2 & 31;
        int j = gi * 64 + wh * 32 + c;
        const float* W = (part == 0) ? Wf : (part == 1) ? Wg : Wh;
        __half v = __float2half_rn(W[(size_t)j * CIN + k]);
        if (k < DIN) wk[(size_t)n * DIN + k] = v;
        else         wr[(size_t)n * HID + (k - DIN)] = v;
    } else if (idx < TOT + N3) {
        int n = idx - TOT;
        int gi = n / 192, rem = n % 192;
        int wh = rem / 96, rem2 = rem % 96, part = rem2 >> 5, c = rem2 & 31;
        int j = gi * 64 + wh * 32 + c;
        bias[n] = ((part == 0) ? bf : (part == 1) ? bg : bh)[j];
    }
}

__global__ void cvtx_k(const float4* __restrict__ x, __half2* __restrict__ xh, int n4) {
    int i = blockIdx.x * blockDim.x + threadIdx.x;
    if (i < n4) {
        float4 v = x[i];
        xh[2 * i]     = __floats2half2_rn(v.x, v.y);
        xh[2 * i + 1] = __floats2half2_rn(v.z, v.w);
    }
}

// ---------------- fp16 warp-MMA GEMM: C[M,3072] = A[M,K] @ Bw[3072,K]^T -----------
// SMEM rows are 64 B (32 halves); 16B chunk c stored at c ^ ((row>>1)&3).
// MODE 0: U = acc + bias (fp16, 128x384 tile).
// MODE 1: pre = acc + U; gate-combine in registers; write h (fp16, 128x128 cols).
template<int K, int MODE>
__global__ __launch_bounds__(THREADS, 1)
void lnn_gemm(const __half* __restrict__ A, const __half* __restrict__ Bw,
              __half* __restrict__ out, const __half* __restrict__ add,
              int addStride, const float* __restrict__ bias) {
    extern __shared__ __align__(1024) char smem[];
    const uint32_t sb = smem_u32(smem);
    const int tid = threadIdx.x, lane = tid & 31, wid = tid >> 5;
    const int wm = wid >> 2, wn = wid & 3;
    const int bn = blockIdx.x, bm = blockIdx.y;

    const __half* Ag = A  + (size_t)bm * BM * K;
    const __half* Bg = Bw + (size_t)bn * BN * K;

    const int lrow = tid >> 2, lch = tid & 3;

    auto load_stage = [&](int s, int kt) {
        uint32_t base = sb + s * STAGE_BYTES;
        {   // A: 128 rows x 4 chunks = 512 = THREADS
            int phys = lch ^ ((lrow >> 1) & 3);
            cpa16(base + lrow * 64 + phys * 16,
                  Ag + (size_t)lrow * K + kt * 32 + lch * 8);
        }
#pragma unroll
        for (int i = 0; i < 3; i++) {   // B: 384 rows x 4 chunks = 1536
            int q = tid + i * THREADS;
            int row = q >> 2, ch = q & 3;
            int phys = ch ^ ((row >> 1) & 3);
            cpa16(base + A_BYTES + row * 64 + phys * 16,
                  Bg + (size_t)row * K + kt * 32 + ch * 8);
        }
    };

    // fragment lane constants
    const int t4 = lane & 3, gq = lane >> 2;
    const int rowA0 = wm * 32 + (lane & 15);
    const int selA  = lane >> 4;                       // k-half for A ldmatrix
    const int laneRowB = (lane & 7) + ((lane >> 4) << 3);
    const int choffB = (lane >> 3) & 1;

    float acc[2][12][4];
#pragma unroll
    for (int a = 0; a < 2; a++)
#pragma unroll
        for (int b = 0; b < 12; b++)
#pragma unroll
            for (int d = 0; d < 4; d++) acc[a][b][d] = 0.f;

    const int KT = K / BK;
    load_stage(0, 0); cp_commit();
    load_stage(1, 1); cp_commit();

    for (int kt = 0; kt < KT; ++kt) {
        cp_wait<1>();
        __syncthreads();
        if (kt + 2 < KT) load_stage((kt + 2) % STAGES, kt + 2);
        cp_commit();

        uint32_t ab = sb + (kt % STAGES) * STAGE_BYTES;
        uint32_t bb = ab + A_BYTES;
#pragma unroll
        for (int k2 = 0; k2 < 2; k2++) {
            uint32_t a0[4], a1[4];
            {
                int r = rowA0;
                uint32_t ph = (uint32_t)((k2 * 2 + selA) ^ ((r >> 1) & 3));
                ldm4(a0, ab + r * 64 + ph * 16);
            }
            {
                int r = rowA0 + 16;
                uint32_t ph = (uint32_t)((k2 * 2 + selA) ^ ((r >> 1) & 3));
                ldm4(a1, ab + r * 64 + ph * 16);
            }
#pragma unroll
            for (int nb = 0; nb < 6; nb++) {
                uint32_t b[4];
                int r = wn * 96 + nb * 16 + laneRowB;
                uint32_t ph = (uint32_t)((k2 * 2 + choffB) ^ ((r >> 1) & 3));
                ldm4(b, bb + r * 64 + ph * 16);
                mma16(acc[0][2 * nb],     a0, b[0], b[1]);
                mma16(acc[1][2 * nb],     a1, b[0], b[1]);
                mma16(acc[0][2 * nb + 1], a0, b[2], b[3]);
                mma16(acc[1][2 * nb + 1], a1, b[2], b[3]);
            }
        }
    }

    if (MODE == 0) {
#pragma unroll
        for (int mt = 0; mt < 2; mt++) {
            int rl = bm * BM + wm * 32 + mt * 16 + gq, rh = rl + 8;
#pragma unroll
            for (int nt = 0; nt < 12; nt++) {
                int col = bn * BN + wn * 96 + nt * 8 + t4 * 2;
                float b0 = bias[col], b1 = bias[col + 1];
                __half2 v0 = __floats2half2_rn(acc[mt][nt][0] + b0, acc[mt][nt][1] + b1);
                __half2 v1 = __floats2half2_rn(acc[mt][nt][2] + b0, acc[mt][nt][3] + b1);
                *(__half2*)(out + (size_t)rl * N3 + col) = v0;
                *(__half2*)(out + (size_t)rh * N3 + col) = v1;
            }
        }
    } else {
        // warp owns matched f/g/h: cols within warp: f=0-31 (nt0-3), g=32-63, h=64-95
        int gcb = (bn * 2 + (wn >> 1)) * 64 + (wn & 1) * 32;   // original hidden col base
        int ub  = bn * BN + wn * 96;                           // U col base (repacked)
#pragma unroll
        for (int mt = 0; mt < 2; mt++) {
            int rl = bm * BM + wm * 32 + mt * 16 + gq, rh = rl + 8;
            const __half* ul = add + (size_t)rl * addStride + ub;
            const __half* uh = add + (size_t)rh * addStride + ub;
#pragma unroll
            for (int j = 0; j < 4; j++) {
                int co = j * 8 + t4 * 2;
                float2 ufl = __half22float2(*(const __half2*)(ul + co));
                float2 ugl = __half22float2(*(const __half2*)(ul + 32 + co));
                float2 uhl = __half22float2(*(const __half2*)(ul + 64 + co));
                float2 ufh = __half22float2(*(const __half2*)(uh + co));
                float2 ugh = __half22float2(*(const __half2*)(uh + 32 + co));
                float2 uhh = __half22float2(*(const __half2*)(uh + 64 + co));
                float o0, o1, o2, o3;
                {
                    float f = acc[mt][j][0] + ufl.x, g = acc[mt][j + 4][0] + ugl.x,
                          h = acc[mt][j + 8][0] + uhl.x;
                    float gate = 1.f / (1.f + expf(f));
                    o0 = h + gate * (g - h);
                }
                {
                    float f = acc[mt][j][1] + ufl.y, g = acc[mt][j + 4][1] + ugl.y,
                          h = acc[mt][j + 8][1] + uhl.y;
                    float gate = 1.f / (1.f + expf(f));
                    o1 = h + gate * (g - h);
                }
                {
                    float f = acc[mt][j][2] + ufh.x, g = acc[mt][j + 4][2] + ugh.x,
                          h = acc[mt][j + 8][2] + uhh.x;
                    float gate = 1.f / (1.f + expf(f));
                    o2 = h + gate * (g - h);
                }
                {
                    float f = acc[mt][j][3] + ufh.y, g = acc[mt][j + 4][3] + ugh.y,
                          h = acc[mt][j + 8][3] + uhh.y;
                    float gate = 1.f / (1.f + expf(f));
                    o3 = h + gate * (g - h);
                }
                *(__half2*)(out + (size_t)rl * HID + gcb + co) = __floats2half2_rn(o0, o1);
                *(__half2*)(out + (size_t)rh * HID + gcb + co) = __floats2half2_rn(o2, o3);
            }
        }
    }
}

// ---------------- step 0 combine (h0 = 0): pre = U[t=0] ---------------------------
__global__ void combine0_k(const __half* __restrict__ U, __half* __restrict__ h0) {
    int idx = blockIdx.x * blockDim.x + threadIdx.x;
    if (idx >= BATCH * HID) return;
    int b = idx >> 10, j = idx & (HID - 1);
    int gi = j >> 6, wh = (j >> 5) & 1, c = j & 31;
    const __half* r = U + (size_t)b * SEQ * N3 + gi * 192 + wh * 96;
    float f = __half2float(r[c]), g = __half2float(r[32 + c]), hh = __half2float(r[64 + c]);
    float gate = 1.f / (1.f + expf(f));
    h0[idx] = __float2half_rn(hh + gate * (g - hh));
}

// ---------------- final FC (fp32 exact) --------------------------------------------
__global__ void final_k(const __half* __restrict__ h, const float* __restrict__ Wfc,
                        const float* __restrict__ bfc, float* __restrict__ out) {
    int b = blockIdx.x;
    float s0 = 0.f, s1 = 0.f;
    for (int j = threadIdx.x; j < HID; j += blockDim.x) {
        float hv = __half2float(h[(size_t)b * HID + j]);
        s0 += hv * Wfc[j];
        s1 += hv * Wfc[HID + j];
    }
#pragma unroll
    for (int o = 16; o > 0; o >>= 1) {
        s0 += __shfl_down_sync(0xFFFFFFFFu, s0, o);
        s1 += __shfl_down_sync(0xFFFFFFFFu, s1, o);
    }
    __shared__ float sm[2][8];
    int warp = threadIdx.x >> 5, lane = threadIdx.x & 31;
    if (lane == 0) { sm[0][warp] = s0; sm[1][warp] = s1; }
    __syncthreads();
    if (threadIdx.x == 0) {
        float t0 = 0.f, t1 = 0.f;
        int nw = blockDim.x >> 5;
        for (int w = 0; w < nw; w++) { t0 += sm[0][w]; t1 += sm[1][w]; }
        out[b * 2 + 0] = t0 + bfc[0];
        out[b * 2 + 1] = t1 + bfc[1];
    }
}

// ---------------- launch -------------------------------------------------------------
extern "C" void kernel_launch(void* const* d_in, const int* in_sizes, int n_in,
                              void* d_out, int out_size) {
    const float* x   = (const float*)d_in[0];
    const float* Wf  = (const float*)d_in[1];
    const float* bf  = (const float*)d_in[2];
    const float* Wg  = (const float*)d_in[3];
    const float* bg  = (const float*)d_in[4];
    const float* Wh  = (const float*)d_in[5];
    const float* bh  = (const float*)d_in[6];
    const float* Wfc = (const float*)d_in[7];
    const float* bfc = (const float*)d_in[8];

    __half *pXh, *pU, *pWk, *pWr, *pH;
    float *pBias;
    cudaGetSymbolAddress((void**)&pXh,  g_Xh);
    cudaGetSymbolAddress((void**)&pU,   g_U);
    cudaGetSymbolAddress((void**)&pWk,  g_Wk);
    cudaGetSymbolAddress((void**)&pWr,  g_Wr);
    cudaGetSymbolAddress((void**)&pBias,g_bias);
    cudaGetSymbolAddress((void**)&pH,   g_H);
    __half* pH0 = pH;
    __half* pH1 = pH + (size_t)BATCH * HID;

    cudaFuncSetAttribute(lnn_gemm<DIN, 0>, cudaFuncAttributeMaxDynamicSharedMemorySize, SMEM_TOTAL);
    cudaFuncSetAttribute(lnn_gemm<HID, 1>, cudaFuncAttributeMaxDynamicSharedMemorySize, SMEM_TOTAL);

    // 1) repack + convert weights; convert x
    {
        int tot = N3 * (DIN + HID) + N3;
        repack_k<<<(tot + 255) / 256, 256>>>(Wf, bf, Wg, bg, Wh, bh, pWk, pWr, pBias);
        int n4 = MT * DIN / 4;
        cvtx_k<<<(n4 + 255) / 256, 256>>>((const float4*)x, (__half2*)pXh, n4);
    }

    // 2) parallel x-part preacts: U = Xh @ Wk^T + bias  (fp16, permuted cols)
    lnn_gemm<DIN, 0><<<dim3(N3 / BN, MT / BM), THREADS, SMEM_TOTAL>>>(
        pXh, pWk, pU, nullptr, 0, pBias);

    // 3) t=0 (h0 = 0)
    combine0_k<<<(BATCH * HID) / 256, 256>>>(pU, pH0);

    // 4) recurrence: single-wave grid (128 CTAs), register-resident gate epilogue
    for (int t = 1; t < SEQ; t++) {
        __half* hprev = ((t - 1) & 1) ? pH1 : pH0;
        __half* hnext = (t & 1) ? pH1 : pH0;
        lnn_gemm<HID, 1><<<dim3(N3 / BN, BATCH / BM), THREADS, SMEM_TOTAL>>>(
            hprev, pWr, hnext, pU + (size_t)t * N3, SEQ * N3, nullptr);
    }

    // 5) final FC
    final_k<<<BATCH, 256>>>(pH1, Wfc, bfc, (float*)d_out);
}